// round 14
// baseline (speedup 1.0000x reference)
#include <cuda_runtime.h>
#include <cuda_fp16.h>
#include <cuda_bf16.h>
#include <cstdint>

// IntEinsum: out[b,t,f] = sum_d x[b,t,d] * (W_int4[d,f] / scale[f])
// GEMM M=1024, K=4096, N=16384, fp32 in/out.
// Round 14: revert bias-fold (precision), keep R12's exact PRMT+SUB
// expansion. BK 64->128, NSTAGE 3->2: halves chunk count -> halves
// mbarrier waits + per-chunk pipeline refill bubbles. Same smem budget
// class (106.6KB, 2 CTA/SM). Raster/epilogue/prepasses from R12.

#define M_DIM 1024
#define N_DIM 16384
#define K_DIM 4096
#define W_ELEMS (K_DIM * N_DIM)

#define BK 128
#define NCHUNK (K_DIM / BK)          // 32
#define NSTAGE 2

#define RS 136                       // A smem row stride (fp16), 272B rows
#define A_PLANE (128 * RS * 2)       // 34816
#define B_RS 144                     // B smem row stride (int8 bytes)
#define B_PLANE (128 * B_RS)         // 18432
#define STAGE_BYTES (A_PLANE + B_PLANE)          // 53248
#define BAR_OFF     (NSTAGE * STAGE_BYTES)       // 106496
#define SMEM_TOTAL  (BAR_OFF + 64)               // 106560

// ---------------- device scratch ----------------
__device__ uint8_t g_w8p[(size_t)N_DIM * K_DIM]; // packed biased permuted int4
__device__ __half  g_a[M_DIM * K_DIM];           // activations fp16
__device__ int g_fmt;

#define FMT_I8      0
#define FMT_I32     1
#define FMT_F32     2
#define FMT_BF16    3
#define FMT_PACKED2 4
#define FMT_PACKED8 5

__device__ __forceinline__ uint32_t smem_u32(const void* p) {
    uint32_t a;
    asm("{ .reg .u64 t; cvta.to.shared.u64 t, %1; cvt.u32.u64 %0, t; }"
        : "=r"(a) : "l"(p));
    return a;
}

// ---------------- format probe (warp-parallel, proven) ----------------
__global__ void probe_kernel(const uint32_t* __restrict__ W, int hint) {
    if (hint >= 0) { if (threadIdx.x == 0) g_fmt = hint; return; }
    const int lane = threadIdx.x;
    uint32_t w0 = W[lane * 2];
    uint32_t w1 = W[lane * 2 + 1];

    bool okf = true;
#pragma unroll
    for (int j = 0; j < 2; j++) {
        float f = __uint_as_float(j ? w1 : w0);
        if (!(f >= -8.f && f <= 7.f) || f != rintf(f)) okf = false;
    }
    if (__all_sync(0xFFFFFFFFu, okf)) { if (lane == 0) g_fmt = FMT_F32; return; }

    bool okb = true;
#pragma unroll
    for (int j = 0; j < 4; j++) {
        uint16_t u = (uint16_t)((j < 2 ? w0 : w1) >> (16 * (j & 1)));
        __nv_bfloat16 b = *reinterpret_cast<__nv_bfloat16*>(&u);
        float f = __bfloat162float(b);
        if (!(f >= -8.f && f <= 7.f) || f != rintf(f)) okb = false;
    }
    if (__all_sync(0xFFFFFFFFu, okb)) { if (lane == 0) g_fmt = FMT_BF16; return; }

    bool oki = ((((int)w0) >> 4) == 0 || (((int)w0) >> 4) == -1) &&
               ((((int)w1) >> 4) == 0 || (((int)w1) >> 4) == -1);
    if (lane == 0) g_fmt = __all_sync(0xFFFFFFFFu, oki) ? FMT_I32 : FMT_I8;
}

__device__ __forceinline__ int sx_nib(uint32_t w, int shift) {
    return ((int)(w << (28 - shift))) >> 28;
}

__device__ __forceinline__ int decode_w(const void* Wv, int fmt, size_t idx) {
    if (fmt == FMT_F32)  return (int)((const float*)Wv)[idx];
    if (fmt == FMT_BF16) return (int)__bfloat162float(((const __nv_bfloat16*)Wv)[idx]);
    if (fmt == FMT_I32)  return sx_nib(((const uint32_t*)Wv)[idx], 0);
    if (fmt == FMT_I8)   return sx_nib((uint32_t)((const uint8_t*)Wv)[idx], 0);
    if (fmt == FMT_PACKED2) {
        uint32_t b = ((const uint8_t*)Wv)[idx >> 1];
        return sx_nib(b, (int)(idx & 1) * 4);
    }
    uint32_t w = ((const uint32_t*)Wv)[idx >> 3];
    return sx_nib(w, (int)(idx & 7) * 4);
}

// ---------------- W convert+pack: [k][n] fmt -> [n][k] biased permuted u8 ----
__global__ void convert_pack_kernel(const void* __restrict__ Wv) {
    const int fmt = g_fmt;
    const int lane = threadIdx.x & 31;
    const int gw = (blockIdx.x * blockDim.x + threadIdx.x) >> 5;
    const int n  = (gw & 511) * 32 + lane;   // 512 n-warps x 32 lanes = 16384
    const int k0 = (gw >> 9) * 32;           // 128 k-blocks of 32

#pragma unroll
    for (int g = 0; g < 2; g++) {
        uint32_t u[16];
#pragma unroll
        for (int j = 0; j < 16; j++)
            u[j] = (uint32_t)(decode_w(Wv, fmt,
                       (size_t)(k0 + g * 16 + j) * N_DIM + n) + 8) & 0xFF;
        uint4 o;
        o.x = u[0] | (u[1] << 8) | (u[8]  << 16) | (u[9]  << 24);
        o.y = u[2] | (u[3] << 8) | (u[10] << 16) | (u[11] << 24);
        o.z = u[4] | (u[5] << 8) | (u[12] << 16) | (u[13] << 24);
        o.w = u[6] | (u[7] << 8) | (u[14] << 16) | (u[15] << 24);
        *reinterpret_cast<uint4*>(&g_w8p[(size_t)n * K_DIM + k0 + g * 16]) = o;
    }
}

// ---------------- A fp32 -> fp16 ----------------
__global__ void a_convert_kernel(const float* __restrict__ A) {
    size_t i = ((size_t)blockIdx.x * blockDim.x + threadIdx.x) * 4;
    float4 v = *reinterpret_cast<const float4*>(&A[i]);
    __half2 h0 = __floats2half2_rn(v.x, v.y);
    __half2 h1 = __floats2half2_rn(v.z, v.w);
    *reinterpret_cast<uint2*>(&g_a[i]) =
        make_uint2(*(uint32_t*)&h0, *(uint32_t*)&h1);
}

// ---------------- MMA / ldmatrix / mbarrier helpers ----------------
__device__ __forceinline__ void mma_f16(float c[4], uint32_t a0, uint32_t a1,
                                        uint32_t a2, uint32_t a3,
                                        uint32_t b0, uint32_t b1) {
    asm volatile(
        "mma.sync.aligned.m16n8k16.row.col.f32.f16.f16.f32 "
        "{%0,%1,%2,%3}, {%4,%5,%6,%7}, {%8,%9}, {%0,%1,%2,%3};\n"
        : "+f"(c[0]), "+f"(c[1]), "+f"(c[2]), "+f"(c[3])
        : "r"(a0), "r"(a1), "r"(a2), "r"(a3), "r"(b0), "r"(b1));
}

// expand packed biased int4x4 -> two fp16x2 regs (EXACT): splice 0x64
// exponent bytes (-> 1024+u), then subtract 1032 in fp16 (exact lattice).
__device__ __forceinline__ void expand_b(uint32_t pk, uint32_t& lo, uint32_t& hi) {
    uint32_t l, h;
    asm("prmt.b32 %0, %2, %3, 0x4140;\n\t"
        "prmt.b32 %1, %2, %3, 0x4342;"
        : "=r"(l), "=r"(h) : "r"(pk), "r"(0x64646464u));
    asm("sub.f16x2 %0, %1, %2;" : "=r"(lo) : "r"(l), "r"(0x64086408u));
    asm("sub.f16x2 %0, %1, %2;" : "=r"(hi) : "r"(h), "r"(0x64086408u));
}

#define LDMATRIX_X4(r0, r1, r2, r3, addr) \
    asm volatile("ldmatrix.sync.aligned.m8n8.x4.shared.b16 {%0,%1,%2,%3}, [%4];" \
        : "=r"(r0), "=r"(r1), "=r"(r2), "=r"(r3) : "r"(addr))

#define CP_ASYNC16(dst, src) \
    asm volatile("cp.async.cg.shared.global [%0], [%1], 16;" \
                 :: "r"(dst), "l"(src) : "memory")
#define CP_MBAR_ARRIVE(addr) \
    asm volatile("cp.async.mbarrier.arrive.noinc.shared.b64 [%0];" \
                 :: "r"(addr) : "memory")

#define MBARRIER_INIT(addr, cnt) \
    asm volatile("mbarrier.init.shared.b64 [%0], %1;" :: "r"(addr), "r"(cnt) : "memory")
#define MBARRIER_ARRIVE(addr) \
    asm volatile("mbarrier.arrive.shared.b64 _, [%0];" :: "r"(addr) : "memory")
#define MBARRIER_WAIT_PARITY(addr, ph) do {                                         \
    uint32_t _m = (addr); uint32_t _p = (ph); uint32_t _d;                          \
    asm volatile("{\n\t.reg .pred p;\n\t"                                           \
        "mbarrier.try_wait.parity.acquire.cta.shared::cta.b64 p, [%1], %2;\n\t"     \
        "selp.b32 %0, 1, 0, p;\n\t}" : "=r"(_d) : "r"(_m), "r"(_p) : "memory");     \
    if (!_d) {                                                                      \
        asm volatile("{\n\t.reg .pred P1;\n\t"                                      \
            "W%=:\n\t"                                                              \
            "mbarrier.try_wait.parity.acquire.cta.shared::cta.b64 P1, [%0], %1, 0x989680;\n\t" \
            "@P1 bra.uni D%=;\n\t"                                                  \
            "bra.uni W%=;\n\t"                                                      \
            "D%=:\n\t}" :: "r"(_m), "r"(_p) : "memory");                            \
    }                                                                               \
} while (0)

// ---------------- GEMM ----------------
__global__ __launch_bounds__(256, 2)
void int4_gemm_kernel(const float* __restrict__ S, float* __restrict__ C) {
    extern __shared__ __align__(128) char smem[];
    const uint32_t smb = smem_u32(smem);

    const int tid    = threadIdx.x;
    const int lane   = tid & 31;
    const int wid    = tid >> 5;
    const int warp_m = wid >> 1;     // 0..3 -> 32 rows
    const int warp_n = wid & 1;      // 0..1 -> 64 cols

    const int bm = blockIdx.x * 128;   // bm-fastest raster (B DRAM once)
    const int bn = blockIdx.y * 128;

    const uint32_t barb = smb + BAR_OFF;
    if (tid == 0) {
#pragma unroll
        for (int s = 0; s < NSTAGE; s++) {
            MBARRIER_INIT(barb + s * 16,     256);  // full
            MBARRIER_INIT(barb + s * 16 + 8, 8);    // empty
        }
    }
    __syncthreads();

    float c[2][8][4];
#pragma unroll
    for (int i = 0; i < 2; i++)
#pragma unroll
        for (int j = 0; j < 8; j++)
#pragma unroll
            for (int q = 0; q < 4; q++) c[i][j][q] = 0.f;

    // A k16 ldmatrix lane offset (RS=136 fp16 -> conflict-free phases)
    const uint32_t aOff =
        (uint32_t)(((warp_m * 32 + ((lane >> 3) & 1) * 8 + (lane & 7)) * RS
                    + ((lane >> 4) & 1) * 8) * 2);
    // B packed int8: x4 mats = n-groups {0,8,16,24} -> row = warp_n*64 + lane
    const uint32_t bOff = (uint32_t)((warp_n * 64 + lane) * B_RS);

    auto issue_stage = [&](int chunk) {
        const uint32_t sb = smb + (uint32_t)(chunk % NSTAGE) * STAGE_BYTES;
        const int k0 = chunk * BK;
        // A: 128 rows x 256B = 2048 x 16B
#pragma unroll
        for (int j = 0; j < 8; j++) {
            const int q  = (tid + j * 256) & 2047;
            const int r  = q >> 4;
            const int cg = q & 15;
            CP_ASYNC16(sb + r * (RS * 2) + cg * 16,
                       &g_a[(size_t)(bm + r) * K_DIM + k0 + cg * 8]);
        }
        // B packed: 128 rows x 128B = 1024 x 16B
#pragma unroll
        for (int j = 0; j < 4; j++) {
            const int q  = (tid + j * 256) & 1023;
            const int r  = q >> 3;
            const int cg = q & 7;
            CP_ASYNC16(sb + A_PLANE + r * B_RS + cg * 16,
                       &g_w8p[(size_t)(bn + r) * K_DIM + k0 + cg * 16]);
        }
    };

#pragma unroll
    for (int p = 0; p < NSTAGE; p++) {
        issue_stage(p);
        CP_MBAR_ARRIVE(barb + p * 16);
    }

    int s = 0, fp = 0;
    for (int i = 0; i < NCHUNK; i++) {
        const uint32_t fullb  = barb + s * 16;
        const uint32_t emptyb = fullb + 8;

        MBARRIER_WAIT_PARITY(fullb, fp);

        const uint32_t sb    = smb + (uint32_t)s * STAGE_BYTES;
        const uint32_t aBase = sb + aOff;
        const uint32_t bBase = sb + A_PLANE + bOff;

#pragma unroll
        for (int kk = 0; kk < 8; kk++) {
            uint32_t a[2][4];
            LDMATRIX_X4(a[0][0], a[0][1], a[0][2], a[0][3], aBase + kk * 32);
            LDMATRIX_X4(a[1][0], a[1][1], a[1][2], a[1][3],
                        aBase + 16 * RS * 2 + kk * 32);

            uint32_t pk[8];
            LDMATRIX_X4(pk[0], pk[1], pk[2], pk[3], bBase + kk * 16);
            LDMATRIX_X4(pk[4], pk[5], pk[6], pk[7],
                        bBase + 32 * B_RS + kk * 16);

            uint32_t be[4][2];
#pragma unroll
            for (int nt = 0; nt < 4; nt++) expand_b(pk[nt], be[nt][0], be[nt][1]);
#pragma unroll
            for (int mt = 0; mt < 2; mt++)
#pragma unroll
                for (int nt = 0; nt < 4; nt++)
                    mma_f16(c[mt][nt], a[mt][0], a[mt][1], a[mt][2], a[mt][3],
                            be[nt][0], be[nt][1]);
#pragma unroll
            for (int nt = 0; nt < 4; nt++) expand_b(pk[nt + 4], be[nt][0], be[nt][1]);
#pragma unroll
            for (int mt = 0; mt < 2; mt++)
#pragma unroll
                for (int nt = 0; nt < 4; nt++)
                    mma_f16(c[mt][nt + 4], a[mt][0], a[mt][1], a[mt][2], a[mt][3],
                            be[nt][0], be[nt][1]);
        }

        if (lane == 0) MBARRIER_ARRIVE(emptyb);

        if (i + NSTAGE < NCHUNK) {
            MBARRIER_WAIT_PARITY(emptyb, fp);
            issue_stage(i + NSTAGE);
            CP_MBAR_ARRIVE(fullb);
        }

        if (++s == NSTAGE) { s = 0; fp ^= 1; }
    }

    // ---- epilogue: out = acc / scale[f] (exact R12 form) ----
    const int row0 = bm + warp_m * 32 + (lane >> 2);
    const int col0 = bn + warp_n * 64 + (lane & 3) * 2;
#pragma unroll
    for (int nt = 0; nt < 8; nt++) {
        int col = col0 + nt * 8;
        float inv0 = 1.0f / S[col];
        float inv1 = 1.0f / S[col + 1];
#pragma unroll
        for (int mt = 0; mt < 2; mt++) {
            int r = row0 + mt * 16;
            float2 v0 = make_float2(c[mt][nt][0] * inv0, c[mt][nt][1] * inv1);
            float2 v1 = make_float2(c[mt][nt][2] * inv0, c[mt][nt][3] * inv1);
            *reinterpret_cast<float2*>(&C[(size_t)r * N_DIM + col])       = v0;
            *reinterpret_cast<float2*>(&C[(size_t)(r + 8) * N_DIM + col]) = v1;
        }
    }
}

// ---------------- launch ----------------
extern "C" void kernel_launch(void* const* d_in, const int* in_sizes, int n_in,
                              void* d_out, int out_size) {
    int ai = 0, si = 2, wi = 1;
    for (int i = 0; i < n_in; i++) {
        if (in_sizes[i] == M_DIM * K_DIM) ai = i;
        else if (in_sizes[i] == N_DIM)    si = i;
        else                              wi = i;
    }
    const float* A = (const float*)d_in[ai];
    const void*  W = d_in[wi];
    const float* S = (const float*)d_in[si];
    float*       C = (float*)d_out;

    int hint = -1;
    if (in_sizes[wi] == W_ELEMS / 2)      hint = FMT_PACKED2;
    else if (in_sizes[wi] == W_ELEMS / 8) hint = FMT_PACKED8;

    static bool attr_done = false;
    if (!attr_done) {
        cudaFuncSetAttribute(int4_gemm_kernel,
                             cudaFuncAttributeMaxDynamicSharedMemorySize, SMEM_TOTAL);
        attr_done = true;
    }

    probe_kernel<<<1, 32>>>((const uint32_t*)W, hint);
    convert_pack_kernel<<<(N_DIM / 32) * (K_DIM / 32) / 8, 256>>>(W);
    a_convert_kernel<<<(M_DIM * K_DIM) / 1024, 256>>>(A);

    dim3 grid(M_DIM / 128, N_DIM / 128);     // (8, 128) -- bm fastest
    int4_gemm_kernel<<<grid, 256, SMEM_TOTAL>>>(S, C);
}

// round 15
// speedup vs baseline: 1.1123x; 1.1123x over previous
#include <cuda_runtime.h>
#include <cuda_fp16.h>
#include <cuda_bf16.h>
#include <cstdint>

// IntEinsum: out[b,t,f] = sum_d x[b,t,d] * (W_int4[d,f] / scale[f])
// GEMM M=1024, K=4096, N=16384, fp32 in/out.
// Round 15: revert R14 (BK=128/2-stage re-coupled warps). R12 core
// restored (BK=64, packed-B PRMT+SUB expansion) with NSTAGE 3->4:
// deeper mbarrier ring = wider warp-drift window, fits 2 CTA/SM
// (114.75KB x 2 = 229.5KB <= 228KB carveout w/ reserve).

#define M_DIM 1024
#define N_DIM 16384
#define K_DIM 4096
#define W_ELEMS (K_DIM * N_DIM)

#define BK 64
#define NCHUNK (K_DIM / BK)          // 64
#define NSTAGE 4

#define RS 72                        // A smem row stride (fp16), 144B rows
#define A_PLANE (128 * RS * 2)       // 18432
#define B_RS 80                      // B smem row stride (int8 bytes) - conflict-free
#define B_PLANE (128 * B_RS)         // 10240
#define STAGE_BYTES (A_PLANE + B_PLANE)          // 28672
#define BAR_OFF     (NSTAGE * STAGE_BYTES)       // 114688
#define SMEM_TOTAL  (BAR_OFF + 64)               // 114752

// ---------------- device scratch ----------------
__device__ uint8_t g_w8p[(size_t)N_DIM * K_DIM]; // packed biased permuted int4
__device__ __half  g_a[M_DIM * K_DIM];           // activations fp16
__device__ int g_fmt;

#define FMT_I8      0
#define FMT_I32     1
#define FMT_F32     2
#define FMT_BF16    3
#define FMT_PACKED2 4
#define FMT_PACKED8 5

__device__ __forceinline__ uint32_t smem_u32(const void* p) {
    uint32_t a;
    asm("{ .reg .u64 t; cvta.to.shared.u64 t, %1; cvt.u32.u64 %0, t; }"
        : "=r"(a) : "l"(p));
    return a;
}

// ---------------- format probe (warp-parallel, proven) ----------------
__global__ void probe_kernel(const uint32_t* __restrict__ W, int hint) {
    if (hint >= 0) { if (threadIdx.x == 0) g_fmt = hint; return; }
    const int lane = threadIdx.x;
    uint32_t w0 = W[lane * 2];
    uint32_t w1 = W[lane * 2 + 1];

    bool okf = true;
#pragma unroll
    for (int j = 0; j < 2; j++) {
        float f = __uint_as_float(j ? w1 : w0);
        if (!(f >= -8.f && f <= 7.f) || f != rintf(f)) okf = false;
    }
    if (__all_sync(0xFFFFFFFFu, okf)) { if (lane == 0) g_fmt = FMT_F32; return; }

    bool okb = true;
#pragma unroll
    for (int j = 0; j < 4; j++) {
        uint16_t u = (uint16_t)((j < 2 ? w0 : w1) >> (16 * (j & 1)));
        __nv_bfloat16 b = *reinterpret_cast<__nv_bfloat16*>(&u);
        float f = __bfloat162float(b);
        if (!(f >= -8.f && f <= 7.f) || f != rintf(f)) okb = false;
    }
    if (__all_sync(0xFFFFFFFFu, okb)) { if (lane == 0) g_fmt = FMT_BF16; return; }

    bool oki = ((((int)w0) >> 4) == 0 || (((int)w0) >> 4) == -1) &&
               ((((int)w1) >> 4) == 0 || (((int)w1) >> 4) == -1);
    if (lane == 0) g_fmt = __all_sync(0xFFFFFFFFu, oki) ? FMT_I32 : FMT_I8;
}

__device__ __forceinline__ int sx_nib(uint32_t w, int shift) {
    return ((int)(w << (28 - shift))) >> 28;
}

__device__ __forceinline__ int decode_w(const void* Wv, int fmt, size_t idx) {
    if (fmt == FMT_F32)  return (int)((const float*)Wv)[idx];
    if (fmt == FMT_BF16) return (int)__bfloat162float(((const __nv_bfloat16*)Wv)[idx]);
    if (fmt == FMT_I32)  return sx_nib(((const uint32_t*)Wv)[idx], 0);
    if (fmt == FMT_I8)   return sx_nib((uint32_t)((const uint8_t*)Wv)[idx], 0);
    if (fmt == FMT_PACKED2) {
        uint32_t b = ((const uint8_t*)Wv)[idx >> 1];
        return sx_nib(b, (int)(idx & 1) * 4);
    }
    uint32_t w = ((const uint32_t*)Wv)[idx >> 3];
    return sx_nib(w, (int)(idx & 7) * 4);
}

// ---------------- W convert+pack: [k][n] fmt -> [n][k] biased permuted u8 ----
__global__ void convert_pack_kernel(const void* __restrict__ Wv) {
    const int fmt = g_fmt;
    const int lane = threadIdx.x & 31;
    const int gw = (blockIdx.x * blockDim.x + threadIdx.x) >> 5;
    const int n  = (gw & 511) * 32 + lane;   // 512 n-warps x 32 lanes = 16384
    const int k0 = (gw >> 9) * 32;           // 128 k-blocks of 32

#pragma unroll
    for (int g = 0; g < 2; g++) {
        uint32_t u[16];
#pragma unroll
        for (int j = 0; j < 16; j++)
            u[j] = (uint32_t)(decode_w(Wv, fmt,
                       (size_t)(k0 + g * 16 + j) * N_DIM + n) + 8) & 0xFF;
        uint4 o;
        o.x = u[0] | (u[1] << 8) | (u[8]  << 16) | (u[9]  << 24);
        o.y = u[2] | (u[3] << 8) | (u[10] << 16) | (u[11] << 24);
        o.z = u[4] | (u[5] << 8) | (u[12] << 16) | (u[13] << 24);
        o.w = u[6] | (u[7] << 8) | (u[14] << 16) | (u[15] << 24);
        *reinterpret_cast<uint4*>(&g_w8p[(size_t)n * K_DIM + k0 + g * 16]) = o;
    }
}

// ---------------- A fp32 -> fp16 ----------------
__global__ void a_convert_kernel(const float* __restrict__ A) {
    size_t i = ((size_t)blockIdx.x * blockDim.x + threadIdx.x) * 4;
    float4 v = *reinterpret_cast<const float4*>(&A[i]);
    __half2 h0 = __floats2half2_rn(v.x, v.y);
    __half2 h1 = __floats2half2_rn(v.z, v.w);
    *reinterpret_cast<uint2*>(&g_a[i]) =
        make_uint2(*(uint32_t*)&h0, *(uint32_t*)&h1);
}

// ---------------- MMA / ldmatrix / mbarrier helpers ----------------
__device__ __forceinline__ void mma_f16(float c[4], uint32_t a0, uint32_t a1,
                                        uint32_t a2, uint32_t a3,
                                        uint32_t b0, uint32_t b1) {
    asm volatile(
        "mma.sync.aligned.m16n8k16.row.col.f32.f16.f16.f32 "
        "{%0,%1,%2,%3}, {%4,%5,%6,%7}, {%8,%9}, {%0,%1,%2,%3};\n"
        : "+f"(c[0]), "+f"(c[1]), "+f"(c[2]), "+f"(c[3])
        : "r"(a0), "r"(a1), "r"(a2), "r"(a3), "r"(b0), "r"(b1));
}

// expand packed biased int4x4 -> two fp16x2 regs (EXACT): splice 0x64
// exponent bytes (-> 1024+u), subtract 1032 in fp16 (exact lattice).
__device__ __forceinline__ void expand_b(uint32_t pk, uint32_t& lo, uint32_t& hi) {
    uint32_t l, h;
    asm("prmt.b32 %0, %2, %3, 0x4140;\n\t"
        "prmt.b32 %1, %2, %3, 0x4342;"
        : "=r"(l), "=r"(h) : "r"(pk), "r"(0x64646464u));
    asm("sub.f16x2 %0, %1, %2;" : "=r"(lo) : "r"(l), "r"(0x64086408u));
    asm("sub.f16x2 %0, %1, %2;" : "=r"(hi) : "r"(h), "r"(0x64086408u));
}

#define LDMATRIX_X4(r0, r1, r2, r3, addr) \
    asm volatile("ldmatrix.sync.aligned.m8n8.x4.shared.b16 {%0,%1,%2,%3}, [%4];" \
        : "=r"(r0), "=r"(r1), "=r"(r2), "=r"(r3) : "r"(addr))

#define CP_ASYNC16(dst, src) \
    asm volatile("cp.async.cg.shared.global [%0], [%1], 16;" \
                 :: "r"(dst), "l"(src) : "memory")
#define CP_MBAR_ARRIVE(addr) \
    asm volatile("cp.async.mbarrier.arrive.noinc.shared.b64 [%0];" \
                 :: "r"(addr) : "memory")

#define MBARRIER_INIT(addr, cnt) \
    asm volatile("mbarrier.init.shared.b64 [%0], %1;" :: "r"(addr), "r"(cnt) : "memory")
#define MBARRIER_ARRIVE(addr) \
    asm volatile("mbarrier.arrive.shared.b64 _, [%0];" :: "r"(addr) : "memory")
#define MBARRIER_WAIT_PARITY(addr, ph) do {                                         \
    uint32_t _m = (addr); uint32_t _p = (ph); uint32_t _d;                          \
    asm volatile("{\n\t.reg .pred p;\n\t"                                           \
        "mbarrier.try_wait.parity.acquire.cta.shared::cta.b64 p, [%1], %2;\n\t"     \
        "selp.b32 %0, 1, 0, p;\n\t}" : "=r"(_d) : "r"(_m), "r"(_p) : "memory");     \
    if (!_d) {                                                                      \
        asm volatile("{\n\t.reg .pred P1;\n\t"                                      \
            "W%=:\n\t"                                                              \
            "mbarrier.try_wait.parity.acquire.cta.shared::cta.b64 P1, [%0], %1, 0x989680;\n\t" \
            "@P1 bra.uni D%=;\n\t"                                                  \
            "bra.uni W%=;\n\t"                                                      \
            "D%=:\n\t}" :: "r"(_m), "r"(_p) : "memory");                            \
    }                                                                               \
} while (0)

// ---------------- GEMM ----------------
__global__ __launch_bounds__(256, 2)
void int4_gemm_kernel(const float* __restrict__ S, float* __restrict__ C) {
    extern __shared__ __align__(128) char smem[];
    const uint32_t smb = smem_u32(smem);

    const int tid    = threadIdx.x;
    const int lane   = tid & 31;
    const int wid    = tid >> 5;
    const int warp_m = wid >> 1;     // 0..3 -> 32 rows
    const int warp_n = wid & 1;      // 0..1 -> 64 cols

    const int bm = blockIdx.x * 128;   // bm-fastest raster (B DRAM once)
    const int bn = blockIdx.y * 128;

    const uint32_t barb = smb + BAR_OFF;
    if (tid == 0) {
#pragma unroll
        for (int s = 0; s < NSTAGE; s++) {
            MBARRIER_INIT(barb + s * 16,     256);  // full
            MBARRIER_INIT(barb + s * 16 + 8, 8);    // empty
        }
    }
    __syncthreads();

    float c[2][8][4];
#pragma unroll
    for (int i = 0; i < 2; i++)
#pragma unroll
        for (int j = 0; j < 8; j++)
#pragma unroll
            for (int q = 0; q < 4; q++) c[i][j][q] = 0.f;

    // A k16 ldmatrix lane offset (proven R7/R8)
    const uint32_t aOff =
        (uint32_t)(((warp_m * 32 + ((lane >> 3) & 1) * 8 + (lane & 7)) * RS
                    + ((lane >> 4) & 1) * 8) * 2);
    // B packed int8: x4 mats = n-groups {0,8,16,24} -> row = warp_n*64 + lane
    const uint32_t bOff = (uint32_t)((warp_n * 64 + lane) * B_RS);

    auto issue_stage = [&](int chunk) {
        const uint32_t sb = smb + (uint32_t)(chunk % NSTAGE) * STAGE_BYTES;
        const int k0 = chunk * BK;
        // A: 1024 x 16B
#pragma unroll
        for (int j = 0; j < 4; j++) {
            const int q  = (tid + j * 256) & 1023;
            const int r  = q >> 3;
            const int cg = q & 7;
            CP_ASYNC16(sb + r * (RS * 2) + cg * 16,
                       &g_a[(size_t)(bm + r) * K_DIM + k0 + cg * 8]);
        }
        // B packed: 512 x 16B (128 rows x 64B)
#pragma unroll
        for (int j = 0; j < 2; j++) {
            const int q  = (tid + j * 256) & 511;
            const int r  = q >> 2;
            const int cg = q & 3;
            CP_ASYNC16(sb + A_PLANE + r * B_RS + cg * 16,
                       &g_w8p[(size_t)(bn + r) * K_DIM + k0 + cg * 16]);
        }
    };

#pragma unroll
    for (int p = 0; p < NSTAGE; p++) {
        issue_stage(p);
        CP_MBAR_ARRIVE(barb + p * 16);
    }

    int s = 0, fp = 0;
    for (int i = 0; i < NCHUNK; i++) {
        const uint32_t fullb  = barb + s * 16;
        const uint32_t emptyb = fullb + 8;

        MBARRIER_WAIT_PARITY(fullb, fp);

        const uint32_t sb    = smb + (uint32_t)s * STAGE_BYTES;
        const uint32_t aBase = sb + aOff;
        const uint32_t bBase = sb + A_PLANE + bOff;

#pragma unroll
        for (int kk = 0; kk < 4; kk++) {
            uint32_t a[2][4];
            LDMATRIX_X4(a[0][0], a[0][1], a[0][2], a[0][3], aBase + kk * 32);
            LDMATRIX_X4(a[1][0], a[1][1], a[1][2], a[1][3],
                        aBase + 16 * RS * 2 + kk * 32);

            uint32_t pk[8];
            LDMATRIX_X4(pk[0], pk[1], pk[2], pk[3], bBase + kk * 16);
            LDMATRIX_X4(pk[4], pk[5], pk[6], pk[7],
                        bBase + 32 * B_RS + kk * 16);

            uint32_t be[4][2];
#pragma unroll
            for (int nt = 0; nt < 4; nt++) expand_b(pk[nt], be[nt][0], be[nt][1]);
#pragma unroll
            for (int mt = 0; mt < 2; mt++)
#pragma unroll
                for (int nt = 0; nt < 4; nt++)
                    mma_f16(c[mt][nt], a[mt][0], a[mt][1], a[mt][2], a[mt][3],
                            be[nt][0], be[nt][1]);
#pragma unroll
            for (int nt = 0; nt < 4; nt++) expand_b(pk[nt + 4], be[nt][0], be[nt][1]);
#pragma unroll
            for (int mt = 0; mt < 2; mt++)
#pragma unroll
                for (int nt = 0; nt < 4; nt++)
                    mma_f16(c[mt][nt + 4], a[mt][0], a[mt][1], a[mt][2], a[mt][3],
                            be[nt][0], be[nt][1]);
        }

        if (lane == 0) MBARRIER_ARRIVE(emptyb);

        if (i + NSTAGE < NCHUNK) {
            MBARRIER_WAIT_PARITY(emptyb, fp);
            issue_stage(i + NSTAGE);
            CP_MBAR_ARRIVE(fullb);
        }

        if (++s == NSTAGE) { s = 0; fp ^= 1; }
    }

    // ---- epilogue: out = acc / scale[f] ----
    const int row0 = bm + warp_m * 32 + (lane >> 2);
    const int col0 = bn + warp_n * 64 + (lane & 3) * 2;
#pragma unroll
    for (int nt = 0; nt < 8; nt++) {
        int col = col0 + nt * 8;
        float inv0 = 1.0f / S[col];
        float inv1 = 1.0f / S[col + 1];
#pragma unroll
        for (int mt = 0; mt < 2; mt++) {
            int r = row0 + mt * 16;
            float2 v0 = make_float2(c[mt][nt][0] * inv0, c[mt][nt][1] * inv1);
            float2 v1 = make_float2(c[mt][nt][2] * inv0, c[mt][nt][3] * inv1);
            *reinterpret_cast<float2*>(&C[(size_t)r * N_DIM + col])       = v0;
            *reinterpret_cast<float2*>(&C[(size_t)(r + 8) * N_DIM + col]) = v1;
        }
    }
}

// ---------------- launch ----------------
extern "C" void kernel_launch(void* const* d_in, const int* in_sizes, int n_in,
                              void* d_out, int out_size) {
    int ai = 0, si = 2, wi = 1;
    for (int i = 0; i < n_in; i++) {
        if (in_sizes[i] == M_DIM * K_DIM) ai = i;
        else if (in_sizes[i] == N_DIM)    si = i;
        else                              wi = i;
    }
    const float* A = (const float*)d_in[ai];
    const void*  W = d_in[wi];
    const float* S = (const float*)d_in[si];
    float*       C = (float*)d_out;

    int hint = -1;
    if (in_sizes[wi] == W_ELEMS / 2)      hint = FMT_PACKED2;
    else if (in_sizes[wi] == W_ELEMS / 8) hint = FMT_PACKED8;

    static bool attr_done = false;
    if (!attr_done) {
        cudaFuncSetAttribute(int4_gemm_kernel,
                             cudaFuncAttributeMaxDynamicSharedMemorySize, SMEM_TOTAL);
        attr_done = true;
    }

    probe_kernel<<<1, 32>>>((const uint32_t*)W, hint);
    convert_pack_kernel<<<(N_DIM / 32) * (K_DIM / 32) / 8, 256>>>(W);
    a_convert_kernel<<<(M_DIM * K_DIM) / 1024, 256>>>(A);

    dim3 grid(M_DIM / 128, N_DIM / 128);     // (8, 128) -- bm fastest
    int4_gemm_kernel<<<grid, 256, SMEM_TOTAL>>>(S, C);
}

// round 16
// speedup vs baseline: 1.1228x; 1.0094x over previous
#include <cuda_runtime.h>
#include <cuda_fp16.h>
#include <cuda_bf16.h>
#include <cstdint>

// IntEinsum: out[b,t,f] = sum_d x[b,t,d] * (W_int4[d,f] / scale[f])
// GEMM M=1024, K=4096, N=16384, fp32 in/out.
// Round 16: small-carrier bias fold. Pack stores (w+8)<<4; PRMT splice of
// 0x54 gives EXACT fp16 (64+u). MMA accumulates carrier 64+u; epilogue
// subtracts 72*rowsum(a). Extra fp32 error calibrated from R13 measurement:
// 11.2e-4 * (72/1032) ~ 0.8e-4 -> total ~2.2e-4. Deletes all SUB.f16x2.
// Core config = R12 (best: BK=64, NSTAGE=3, packed B, bm-fastest raster).

#define M_DIM 1024
#define N_DIM 16384
#define K_DIM 4096
#define W_ELEMS (K_DIM * N_DIM)

#define BK 64
#define NCHUNK (K_DIM / BK)          // 64
#define NSTAGE 3

#define RS 72                        // A smem row stride (fp16), 144B rows
#define A_PLANE (128 * RS * 2)       // 18432
#define B_RS 80                      // B smem row stride (int8 bytes)
#define B_PLANE (128 * B_RS)         // 10240
#define STAGE_BYTES (A_PLANE + B_PLANE)          // 28672
#define BAR_OFF     (NSTAGE * STAGE_BYTES)       // 86016
#define SMEM_TOTAL  (BAR_OFF + 64)

// ---------------- device scratch ----------------
__device__ uint8_t g_w8p[(size_t)N_DIM * K_DIM]; // (w+8)<<4, permuted, [n][k]
__device__ __half  g_a[M_DIM * K_DIM];           // activations fp16
__device__ float   g_rsum[M_DIM];                // per-row sum of fp16 A
__device__ int g_fmt;

#define FMT_I8      0
#define FMT_I32     1
#define FMT_F32     2
#define FMT_BF16    3
#define FMT_PACKED2 4
#define FMT_PACKED8 5

__device__ __forceinline__ uint32_t smem_u32(const void* p) {
    uint32_t a;
    asm("{ .reg .u64 t; cvta.to.shared.u64 t, %1; cvt.u32.u64 %0, t; }"
        : "=r"(a) : "l"(p));
    return a;
}

// ---------------- format probe (warp-parallel, proven) ----------------
__global__ void probe_kernel(const uint32_t* __restrict__ W, int hint) {
    if (hint >= 0) { if (threadIdx.x == 0) g_fmt = hint; return; }
    const int lane = threadIdx.x;
    uint32_t w0 = W[lane * 2];
    uint32_t w1 = W[lane * 2 + 1];

    bool okf = true;
#pragma unroll
    for (int j = 0; j < 2; j++) {
        float f = __uint_as_float(j ? w1 : w0);
        if (!(f >= -8.f && f <= 7.f) || f != rintf(f)) okf = false;
    }
    if (__all_sync(0xFFFFFFFFu, okf)) { if (lane == 0) g_fmt = FMT_F32; return; }

    bool okb = true;
#pragma unroll
    for (int j = 0; j < 4; j++) {
        uint16_t u = (uint16_t)((j < 2 ? w0 : w1) >> (16 * (j & 1)));
        __nv_bfloat16 b = *reinterpret_cast<__nv_bfloat16*>(&u);
        float f = __bfloat162float(b);
        if (!(f >= -8.f && f <= 7.f) || f != rintf(f)) okb = false;
    }
    if (__all_sync(0xFFFFFFFFu, okb)) { if (lane == 0) g_fmt = FMT_BF16; return; }

    bool oki = ((((int)w0) >> 4) == 0 || (((int)w0) >> 4) == -1) &&
               ((((int)w1) >> 4) == 0 || (((int)w1) >> 4) == -1);
    if (lane == 0) g_fmt = __all_sync(0xFFFFFFFFu, oki) ? FMT_I32 : FMT_I8;
}

__device__ __forceinline__ int sx_nib(uint32_t w, int shift) {
    return ((int)(w << (28 - shift))) >> 28;
}

__device__ __forceinline__ int decode_w(const void* Wv, int fmt, size_t idx) {
    if (fmt == FMT_F32)  return (int)((const float*)Wv)[idx];
    if (fmt == FMT_BF16) return (int)__bfloat162float(((const __nv_bfloat16*)Wv)[idx]);
    if (fmt == FMT_I32)  return sx_nib(((const uint32_t*)Wv)[idx], 0);
    if (fmt == FMT_I8)   return sx_nib((uint32_t)((const uint8_t*)Wv)[idx], 0);
    if (fmt == FMT_PACKED2) {
        uint32_t b = ((const uint8_t*)Wv)[idx >> 1];
        return sx_nib(b, (int)(idx & 1) * 4);
    }
    uint32_t w = ((const uint32_t*)Wv)[idx >> 3];
    return sx_nib(w, (int)(idx & 7) * 4);
}

// ---------------- W convert+pack: [k][n] fmt -> [n][k] (w+8)<<4 permuted ----
__global__ void convert_pack_kernel(const void* __restrict__ Wv) {
    const int fmt = g_fmt;
    const int lane = threadIdx.x & 31;
    const int gw = (blockIdx.x * blockDim.x + threadIdx.x) >> 5;
    const int n  = (gw & 511) * 32 + lane;   // 512 n-warps x 32 lanes = 16384
    const int k0 = (gw >> 9) * 32;           // 128 k-blocks of 32

#pragma unroll
    for (int g = 0; g < 2; g++) {
        uint32_t u[16];
#pragma unroll
        for (int j = 0; j < 16; j++)
            u[j] = ((uint32_t)(decode_w(Wv, fmt,
                       (size_t)(k0 + g * 16 + j) * N_DIM + n) + 8) << 4) & 0xFF;
        uint4 o;
        o.x = u[0] | (u[1] << 8) | (u[8]  << 16) | (u[9]  << 24);
        o.y = u[2] | (u[3] << 8) | (u[10] << 16) | (u[11] << 24);
        o.z = u[4] | (u[5] << 8) | (u[12] << 16) | (u[13] << 24);
        o.w = u[6] | (u[7] << 8) | (u[14] << 16) | (u[15] << 24);
        *reinterpret_cast<uint4*>(&g_w8p[(size_t)n * K_DIM + k0 + g * 16]) = o;
    }
}

// ---------------- A fp32 -> fp16 ----------------
__global__ void a_convert_kernel(const float* __restrict__ A) {
    size_t i = ((size_t)blockIdx.x * blockDim.x + threadIdx.x) * 4;
    float4 v = *reinterpret_cast<const float4*>(&A[i]);
    __half2 h0 = __floats2half2_rn(v.x, v.y);
    __half2 h1 = __floats2half2_rn(v.z, v.w);
    *reinterpret_cast<uint2*>(&g_a[i]) =
        make_uint2(*(uint32_t*)&h0, *(uint32_t*)&h1);
}

// ---------------- per-row sum of fp16 A (bias-fold correction) ----------
__global__ void a_rowsum_kernel() {
    const int lane = threadIdx.x & 31;
    const int row  = (blockIdx.x * blockDim.x + threadIdx.x) >> 5;
    const __half* r = &g_a[(size_t)row * K_DIM];
    float s = 0.f;
#pragma unroll
    for (int j = 0; j < 32; j++) {
        uint2 p = *reinterpret_cast<const uint2*>(&r[j * 128 + lane * 4]);
        __half2 h0 = *reinterpret_cast<__half2*>(&p.x);
        __half2 h1 = *reinterpret_cast<__half2*>(&p.y);
        float2 f0 = __half22float2(h0);
        float2 f1 = __half22float2(h1);
        s += (f0.x + f0.y) + (f1.x + f1.y);
    }
#pragma unroll
    for (int o = 16; o > 0; o >>= 1)
        s += __shfl_xor_sync(0xFFFFFFFFu, s, o);
    if (lane == 0) g_rsum[row] = s;
}

// ---------------- MMA / ldmatrix / mbarrier helpers ----------------
__device__ __forceinline__ void mma_f16(float c[4], uint32_t a0, uint32_t a1,
                                        uint32_t a2, uint32_t a3,
                                        uint32_t b0, uint32_t b1) {
    asm volatile(
        "mma.sync.aligned.m16n8k16.row.col.f32.f16.f16.f32 "
        "{%0,%1,%2,%3}, {%4,%5,%6,%7}, {%8,%9}, {%0,%1,%2,%3};\n"
        : "+f"(c[0]), "+f"(c[1]), "+f"(c[2]), "+f"(c[3])
        : "r"(a0), "r"(a1), "r"(a2), "r"(a3), "r"(b0), "r"(b1));
}

// expand packed (w+8)<<4 bytes -> two fp16x2 regs holding EXACT (64+w+8):
// fp16 bits 0x54|m with m = 16u -> 2^6*(1+16u/1024) = 64+u. PRMT only.
__device__ __forceinline__ void expand_b(uint32_t pk, uint32_t& lo, uint32_t& hi) {
    asm("prmt.b32 %0, %2, %3, 0x4140;\n\t"
        "prmt.b32 %1, %2, %3, 0x4342;"
        : "=r"(lo), "=r"(hi) : "r"(pk), "r"(0x54545454u));
}

#define LDMATRIX_X4(r0, r1, r2, r3, addr) \
    asm volatile("ldmatrix.sync.aligned.m8n8.x4.shared.b16 {%0,%1,%2,%3}, [%4];" \
        : "=r"(r0), "=r"(r1), "=r"(r2), "=r"(r3) : "r"(addr))

#define CP_ASYNC16(dst, src) \
    asm volatile("cp.async.cg.shared.global [%0], [%1], 16;" \
                 :: "r"(dst), "l"(src) : "memory")
#define CP_MBAR_ARRIVE(addr) \
    asm volatile("cp.async.mbarrier.arrive.noinc.shared.b64 [%0];" \
                 :: "r"(addr) : "memory")

#define MBARRIER_INIT(addr, cnt) \
    asm volatile("mbarrier.init.shared.b64 [%0], %1;" :: "r"(addr), "r"(cnt) : "memory")
#define MBARRIER_ARRIVE(addr) \
    asm volatile("mbarrier.arrive.shared.b64 _, [%0];" :: "r"(addr) : "memory")
#define MBARRIER_WAIT_PARITY(addr, ph) do {                                         \
    uint32_t _m = (addr); uint32_t _p = (ph); uint32_t _d;                          \
    asm volatile("{\n\t.reg .pred p;\n\t"                                           \
        "mbarrier.try_wait.parity.acquire.cta.shared::cta.b64 p, [%1], %2;\n\t"     \
        "selp.b32 %0, 1, 0, p;\n\t}" : "=r"(_d) : "r"(_m), "r"(_p) : "memory");     \
    if (!_d) {                                                                      \
        asm volatile("{\n\t.reg .pred P1;\n\t"                                      \
            "W%=:\n\t"                                                              \
            "mbarrier.try_wait.parity.acquire.cta.shared::cta.b64 P1, [%0], %1, 0x989680;\n\t" \
            "@P1 bra.uni D%=;\n\t"                                                  \
            "bra.uni W%=;\n\t"                                                      \
            "D%=:\n\t}" :: "r"(_m), "r"(_p) : "memory");                            \
    }                                                                               \
} while (0)

// ---------------- GEMM ----------------
__global__ __launch_bounds__(256, 2)
void int4_gemm_kernel(const float* __restrict__ S, float* __restrict__ C) {
    extern __shared__ __align__(128) char smem[];
    const uint32_t smb = smem_u32(smem);

    const int tid    = threadIdx.x;
    const int lane   = tid & 31;
    const int wid    = tid >> 5;
    const int warp_m = wid >> 1;     // 0..3 -> 32 rows
    const int warp_n = wid & 1;      // 0..1 -> 64 cols

    const int bm = blockIdx.x * 128;   // bm-fastest raster (B DRAM once)
    const int bn = blockIdx.y * 128;

    const uint32_t barb = smb + BAR_OFF;
    if (tid == 0) {
#pragma unroll
        for (int s = 0; s < NSTAGE; s++) {
            MBARRIER_INIT(barb + s * 16,     256);  // full
            MBARRIER_INIT(barb + s * 16 + 8, 8);    // empty
        }
    }
    __syncthreads();

    float c[2][8][4];
#pragma unroll
    for (int i = 0; i < 2; i++)
#pragma unroll
        for (int j = 0; j < 8; j++)
#pragma unroll
            for (int q = 0; q < 4; q++) c[i][j][q] = 0.f;

    const uint32_t aOff =
        (uint32_t)(((warp_m * 32 + ((lane >> 3) & 1) * 8 + (lane & 7)) * RS
                    + ((lane >> 4) & 1) * 8) * 2);
    const uint32_t bOff = (uint32_t)((warp_n * 64 + lane) * B_RS);

    auto issue_stage = [&](int chunk) {
        const uint32_t sb = smb + (uint32_t)(chunk % NSTAGE) * STAGE_BYTES;
        const int k0 = chunk * BK;
#pragma unroll
        for (int j = 0; j < 4; j++) {
            const int q  = (tid + j * 256) & 1023;
            const int r  = q >> 3;
            const int cg = q & 7;
            CP_ASYNC16(sb + r * (RS * 2) + cg * 16,
                       &g_a[(size_t)(bm + r) * K_DIM + k0 + cg * 8]);
        }
#pragma unroll
        for (int j = 0; j < 2; j++) {
            const int q  = (tid + j * 256) & 511;
            const int r  = q >> 2;
            const int cg = q & 3;
            CP_ASYNC16(sb + A_PLANE + r * B_RS + cg * 16,
                       &g_w8p[(size_t)(bn + r) * K_DIM + k0 + cg * 16]);
        }
    };

#pragma unroll
    for (int p = 0; p < NSTAGE; p++) {
        issue_stage(p);
        CP_MBAR_ARRIVE(barb + p * 16);
    }

    int s = 0, fp = 0;
    for (int i = 0; i < NCHUNK; i++) {
        const uint32_t fullb  = barb + s * 16;
        const uint32_t emptyb = fullb + 8;

        MBARRIER_WAIT_PARITY(fullb, fp);

        const uint32_t sb    = smb + (uint32_t)s * STAGE_BYTES;
        const uint32_t aBase = sb + aOff;
        const uint32_t bBase = sb + A_PLANE + bOff;

#pragma unroll
        for (int kk = 0; kk < 4; kk++) {
            uint32_t a[2][4];
            LDMATRIX_X4(a[0][0], a[0][1], a[0][2], a[0][3], aBase + kk * 32);
            LDMATRIX_X4(a[1][0], a[1][1], a[1][2], a[1][3],
                        aBase + 16 * RS * 2 + kk * 32);

            uint32_t pk[8];
            LDMATRIX_X4(pk[0], pk[1], pk[2], pk[3], bBase + kk * 16);
            LDMATRIX_X4(pk[4], pk[5], pk[6], pk[7],
                        bBase + 32 * B_RS + kk * 16);

            uint32_t be[4][2];
#pragma unroll
            for (int nt = 0; nt < 4; nt++) expand_b(pk[nt], be[nt][0], be[nt][1]);
#pragma unroll
            for (int mt = 0; mt < 2; mt++)
#pragma unroll
                for (int nt = 0; nt < 4; nt++)
                    mma_f16(c[mt][nt], a[mt][0], a[mt][1], a[mt][2], a[mt][3],
                            be[nt][0], be[nt][1]);
#pragma unroll
            for (int nt = 0; nt < 4; nt++) expand_b(pk[nt + 4], be[nt][0], be[nt][1]);
#pragma unroll
            for (int mt = 0; mt < 2; mt++)
#pragma unroll
                for (int nt = 0; nt < 4; nt++)
                    mma_f16(c[mt][nt + 4], a[mt][0], a[mt][1], a[mt][2], a[mt][3],
                            be[nt][0], be[nt][1]);
        }

        if (lane == 0) MBARRIER_ARRIVE(emptyb);

        if (i + NSTAGE < NCHUNK) {
            MBARRIER_WAIT_PARITY(emptyb, fp);
            issue_stage(i + NSTAGE);
            CP_MBAR_ARRIVE(fullb);
        }

        if (++s == NSTAGE) { s = 0; fp ^= 1; }
    }

    // ---- epilogue: out = (acc - 72*rowsum) / scale[f] ----
    const int row0 = bm + warp_m * 32 + (lane >> 2);
    const int col0 = bn + warp_n * 64 + (lane & 3) * 2;
#pragma unroll
    for (int mt = 0; mt < 2; mt++) {
        const int r = row0 + mt * 16;
        const float corr0 = 72.0f * g_rsum[r];
        const float corr1 = 72.0f * g_rsum[r + 8];
#pragma unroll
        for (int nt = 0; nt < 8; nt++) {
            int col = col0 + nt * 8;
            float inv0 = 1.0f / S[col];
            float inv1 = 1.0f / S[col + 1];
            float2 v0 = make_float2((c[mt][nt][0] - corr0) * inv0,
                                    (c[mt][nt][1] - corr0) * inv1);
            float2 v1 = make_float2((c[mt][nt][2] - corr1) * inv0,
                                    (c[mt][nt][3] - corr1) * inv1);
            *reinterpret_cast<float2*>(&C[(size_t)r * N_DIM + col])       = v0;
            *reinterpret_cast<float2*>(&C[(size_t)(r + 8) * N_DIM + col]) = v1;
        }
    }
}

// ---------------- launch ----------------
extern "C" void kernel_launch(void* const* d_in, const int* in_sizes, int n_in,
                              void* d_out, int out_size) {
    int ai = 0, si = 2, wi = 1;
    for (int i = 0; i < n_in; i++) {
        if (in_sizes[i] == M_DIM * K_DIM) ai = i;
        else if (in_sizes[i] == N_DIM)    si = i;
        else                              wi = i;
    }
    const float* A = (const float*)d_in[ai];
    const void*  W = d_in[wi];
    const float* S = (const float*)d_in[si];
    float*       C = (float*)d_out;

    int hint = -1;
    if (in_sizes[wi] == W_ELEMS / 2)      hint = FMT_PACKED2;
    else if (in_sizes[wi] == W_ELEMS / 8) hint = FMT_PACKED8;

    static bool attr_done = false;
    if (!attr_done) {
        cudaFuncSetAttribute(int4_gemm_kernel,
                             cudaFuncAttributeMaxDynamicSharedMemorySize, SMEM_TOTAL);
        attr_done = true;
    }

    probe_kernel<<<1, 32>>>((const uint32_t*)W, hint);
    convert_pack_kernel<<<(N_DIM / 32) * (K_DIM / 32) / 8, 256>>>(W);
    a_convert_kernel<<<(M_DIM * K_DIM) / 1024, 256>>>(A);
    a_rowsum_kernel<<<(M_DIM * 32) / 256, 256>>>();

    dim3 grid(M_DIM / 128, N_DIM / 128);     // (8, 128) -- bm fastest
    int4_gemm_kernel<<<grid, 256, SMEM_TOTAL>>>(S, C);
}

// round 17
// speedup vs baseline: 1.1304x; 1.0068x over previous
#include <cuda_runtime.h>
#include <cuda_fp16.h>
#include <cuda_bf16.h>
#include <cstdint>

// IntEinsum: out[b,t,f] = sum_d x[b,t,d] * (W_int4[d,f] / scale[f])
// GEMM M=1024, K=4096, N=16384, fp32 in/out.
// Round 17: fuse A-convert + rowsum into one warp-per-row pass (one read
// of A, one launch fewer). GEMM core frozen at R16 (412.0us): BK=64,
// NSTAGE=3, packed B (w+8)<<4 with PRMT-only expansion to exact fp16
// (64+u), epilogue subtracts 72*rowsum(a).

#define M_DIM 1024
#define N_DIM 16384
#define K_DIM 4096
#define W_ELEMS (K_DIM * N_DIM)

#define BK 64
#define NCHUNK (K_DIM / BK)          // 64
#define NSTAGE 3

#define RS 72                        // A smem row stride (fp16), 144B rows
#define A_PLANE (128 * RS * 2)       // 18432
#define B_RS 80                      // B smem row stride (int8 bytes)
#define B_PLANE (128 * B_RS)         // 10240
#define STAGE_BYTES (A_PLANE + B_PLANE)          // 28672
#define BAR_OFF     (NSTAGE * STAGE_BYTES)       // 86016
#define SMEM_TOTAL  (BAR_OFF + 64)

// ---------------- device scratch ----------------
__device__ uint8_t g_w8p[(size_t)N_DIM * K_DIM]; // (w+8)<<4, permuted, [n][k]
__device__ __half  g_a[M_DIM * K_DIM];           // activations fp16
__device__ float   g_rsum[M_DIM];                // per-row sum of fp16 A
__device__ int g_fmt;

#define FMT_I8      0
#define FMT_I32     1
#define FMT_F32     2
#define FMT_BF16    3
#define FMT_PACKED2 4
#define FMT_PACKED8 5

__device__ __forceinline__ uint32_t smem_u32(const void* p) {
    uint32_t a;
    asm("{ .reg .u64 t; cvta.to.shared.u64 t, %1; cvt.u32.u64 %0, t; }"
        : "=r"(a) : "l"(p));
    return a;
}

// ---------------- format probe (warp-parallel, proven) ----------------
__global__ void probe_kernel(const uint32_t* __restrict__ W, int hint) {
    if (hint >= 0) { if (threadIdx.x == 0) g_fmt = hint; return; }
    const int lane = threadIdx.x;
    uint32_t w0 = W[lane * 2];
    uint32_t w1 = W[lane * 2 + 1];

    bool okf = true;
#pragma unroll
    for (int j = 0; j < 2; j++) {
        float f = __uint_as_float(j ? w1 : w0);
        if (!(f >= -8.f && f <= 7.f) || f != rintf(f)) okf = false;
    }
    if (__all_sync(0xFFFFFFFFu, okf)) { if (lane == 0) g_fmt = FMT_F32; return; }

    bool okb = true;
#pragma unroll
    for (int j = 0; j < 4; j++) {
        uint16_t u = (uint16_t)((j < 2 ? w0 : w1) >> (16 * (j & 1)));
        __nv_bfloat16 b = *reinterpret_cast<__nv_bfloat16*>(&u);
        float f = __bfloat162float(b);
        if (!(f >= -8.f && f <= 7.f) || f != rintf(f)) okb = false;
    }
    if (__all_sync(0xFFFFFFFFu, okb)) { if (lane == 0) g_fmt = FMT_BF16; return; }

    bool oki = ((((int)w0) >> 4) == 0 || (((int)w0) >> 4) == -1) &&
               ((((int)w1) >> 4) == 0 || (((int)w1) >> 4) == -1);
    if (lane == 0) g_fmt = __all_sync(0xFFFFFFFFu, oki) ? FMT_I32 : FMT_I8;
}

__device__ __forceinline__ int sx_nib(uint32_t w, int shift) {
    return ((int)(w << (28 - shift))) >> 28;
}

__device__ __forceinline__ int decode_w(const void* Wv, int fmt, size_t idx) {
    if (fmt == FMT_F32)  return (int)((const float*)Wv)[idx];
    if (fmt == FMT_BF16) return (int)__bfloat162float(((const __nv_bfloat16*)Wv)[idx]);
    if (fmt == FMT_I32)  return sx_nib(((const uint32_t*)Wv)[idx], 0);
    if (fmt == FMT_I8)   return sx_nib((uint32_t)((const uint8_t*)Wv)[idx], 0);
    if (fmt == FMT_PACKED2) {
        uint32_t b = ((const uint8_t*)Wv)[idx >> 1];
        return sx_nib(b, (int)(idx & 1) * 4);
    }
    uint32_t w = ((const uint32_t*)Wv)[idx >> 3];
    return sx_nib(w, (int)(idx & 7) * 4);
}

// ---------------- W convert+pack: [k][n] fmt -> [n][k] (w+8)<<4 permuted ----
__global__ void convert_pack_kernel(const void* __restrict__ Wv) {
    const int fmt = g_fmt;
    const int lane = threadIdx.x & 31;
    const int gw = (blockIdx.x * blockDim.x + threadIdx.x) >> 5;
    const int n  = (gw & 511) * 32 + lane;   // 512 n-warps x 32 lanes = 16384
    const int k0 = (gw >> 9) * 32;           // 128 k-blocks of 32

#pragma unroll
    for (int g = 0; g < 2; g++) {
        uint32_t u[16];
#pragma unroll
        for (int j = 0; j < 16; j++)
            u[j] = ((uint32_t)(decode_w(Wv, fmt,
                       (size_t)(k0 + g * 16 + j) * N_DIM + n) + 8) << 4) & 0xFF;
        uint4 o;
        o.x = u[0] | (u[1] << 8) | (u[8]  << 16) | (u[9]  << 24);
        o.y = u[2] | (u[3] << 8) | (u[10] << 16) | (u[11] << 24);
        o.z = u[4] | (u[5] << 8) | (u[12] << 16) | (u[13] << 24);
        o.w = u[6] | (u[7] << 8) | (u[14] << 16) | (u[15] << 24);
        *reinterpret_cast<uint4*>(&g_w8p[(size_t)n * K_DIM + k0 + g * 16]) = o;
    }
}

// ---------------- fused A prep: fp32 -> fp16 + per-row sum (warp/row) ------
__global__ void a_prep_kernel(const float* __restrict__ A) {
    const int lane = threadIdx.x & 31;
    const int row  = (blockIdx.x * blockDim.x + threadIdx.x) >> 5;
    const float* src = &A[(size_t)row * K_DIM];
    __half* dst = &g_a[(size_t)row * K_DIM];

    float s = 0.f;
#pragma unroll
    for (int j = 0; j < 32; j++) {
        const int off = j * 128 + lane * 4;
        float4 v = *reinterpret_cast<const float4*>(&src[off]);
        __half2 h0 = __floats2half2_rn(v.x, v.y);
        __half2 h1 = __floats2half2_rn(v.z, v.w);
        *reinterpret_cast<uint2*>(&dst[off]) =
            make_uint2(*(uint32_t*)&h0, *(uint32_t*)&h1);
        // sum the fp16-rounded values (what the MMA actually accumulates)
        float2 f0 = __half22float2(h0);
        float2 f1 = __half22float2(h1);
        s += (f0.x + f0.y) + (f1.x + f1.y);
    }
#pragma unroll
    for (int o = 16; o > 0; o >>= 1)
        s += __shfl_xor_sync(0xFFFFFFFFu, s, o);
    if (lane == 0) g_rsum[row] = s;
}

// ---------------- MMA / ldmatrix / mbarrier helpers ----------------
__device__ __forceinline__ void mma_f16(float c[4], uint32_t a0, uint32_t a1,
                                        uint32_t a2, uint32_t a3,
                                        uint32_t b0, uint32_t b1) {
    asm volatile(
        "mma.sync.aligned.m16n8k16.row.col.f32.f16.f16.f32 "
        "{%0,%1,%2,%3}, {%4,%5,%6,%7}, {%8,%9}, {%0,%1,%2,%3};\n"
        : "+f"(c[0]), "+f"(c[1]), "+f"(c[2]), "+f"(c[3])
        : "r"(a0), "r"(a1), "r"(a2), "r"(a3), "r"(b0), "r"(b1));
}

// expand packed (w+8)<<4 bytes -> two fp16x2 regs holding EXACT (64+w+8)
__device__ __forceinline__ void expand_b(uint32_t pk, uint32_t& lo, uint32_t& hi) {
    asm("prmt.b32 %0, %2, %3, 0x4140;\n\t"
        "prmt.b32 %1, %2, %3, 0x4342;"
        : "=r"(lo), "=r"(hi) : "r"(pk), "r"(0x54545454u));
}

#define LDMATRIX_X4(r0, r1, r2, r3, addr) \
    asm volatile("ldmatrix.sync.aligned.m8n8.x4.shared.b16 {%0,%1,%2,%3}, [%4];" \
        : "=r"(r0), "=r"(r1), "=r"(r2), "=r"(r3) : "r"(addr))

#define CP_ASYNC16(dst, src) \
    asm volatile("cp.async.cg.shared.global [%0], [%1], 16;" \
                 :: "r"(dst), "l"(src) : "memory")
#define CP_MBAR_ARRIVE(addr) \
    asm volatile("cp.async.mbarrier.arrive.noinc.shared.b64 [%0];" \
                 :: "r"(addr) : "memory")

#define MBARRIER_INIT(addr, cnt) \
    asm volatile("mbarrier.init.shared.b64 [%0], %1;" :: "r"(addr), "r"(cnt) : "memory")
#define MBARRIER_ARRIVE(addr) \
    asm volatile("mbarrier.arrive.shared.b64 _, [%0];" :: "r"(addr) : "memory")
#define MBARRIER_WAIT_PARITY(addr, ph) do {                                         \
    uint32_t _m = (addr); uint32_t _p = (ph); uint32_t _d;                          \
    asm volatile("{\n\t.reg .pred p;\n\t"                                           \
        "mbarrier.try_wait.parity.acquire.cta.shared::cta.b64 p, [%1], %2;\n\t"     \
        "selp.b32 %0, 1, 0, p;\n\t}" : "=r"(_d) : "r"(_m), "r"(_p) : "memory");     \
    if (!_d) {                                                                      \
        asm volatile("{\n\t.reg .pred P1;\n\t"                                      \
            "W%=:\n\t"                                                              \
            "mbarrier.try_wait.parity.acquire.cta.shared::cta.b64 P1, [%0], %1, 0x989680;\n\t" \
            "@P1 bra.uni D%=;\n\t"                                                  \
            "bra.uni W%=;\n\t"                                                      \
            "D%=:\n\t}" :: "r"(_m), "r"(_p) : "memory");                            \
    }                                                                               \
} while (0)

// ---------------- GEMM ----------------
__global__ __launch_bounds__(256, 2)
void int4_gemm_kernel(const float* __restrict__ S, float* __restrict__ C) {
    extern __shared__ __align__(128) char smem[];
    const uint32_t smb = smem_u32(smem);

    const int tid    = threadIdx.x;
    const int lane   = tid & 31;
    const int wid    = tid >> 5;
    const int warp_m = wid >> 1;     // 0..3 -> 32 rows
    const int warp_n = wid & 1;      // 0..1 -> 64 cols

    const int bm = blockIdx.x * 128;   // bm-fastest raster (B DRAM once)
    const int bn = blockIdx.y * 128;

    const uint32_t barb = smb + BAR_OFF;
    if (tid == 0) {
#pragma unroll
        for (int s = 0; s < NSTAGE; s++) {
            MBARRIER_INIT(barb + s * 16,     256);  // full
            MBARRIER_INIT(barb + s * 16 + 8, 8);    // empty
        }
    }
    __syncthreads();

    float c[2][8][4];
#pragma unroll
    for (int i = 0; i < 2; i++)
#pragma unroll
        for (int j = 0; j < 8; j++)
#pragma unroll
            for (int q = 0; q < 4; q++) c[i][j][q] = 0.f;

    const uint32_t aOff =
        (uint32_t)(((warp_m * 32 + ((lane >> 3) & 1) * 8 + (lane & 7)) * RS
                    + ((lane >> 4) & 1) * 8) * 2);
    const uint32_t bOff = (uint32_t)((warp_n * 64 + lane) * B_RS);

    auto issue_stage = [&](int chunk) {
        const uint32_t sb = smb + (uint32_t)(chunk % NSTAGE) * STAGE_BYTES;
        const int k0 = chunk * BK;
#pragma unroll
        for (int j = 0; j < 4; j++) {
            const int q  = (tid + j * 256) & 1023;
            const int r  = q >> 3;
            const int cg = q & 7;
            CP_ASYNC16(sb + r * (RS * 2) + cg * 16,
                       &g_a[(size_t)(bm + r) * K_DIM + k0 + cg * 8]);
        }
#pragma unroll
        for (int j = 0; j < 2; j++) {
            const int q  = (tid + j * 256) & 511;
            const int r  = q >> 2;
            const int cg = q & 3;
            CP_ASYNC16(sb + A_PLANE + r * B_RS + cg * 16,
                       &g_w8p[(size_t)(bn + r) * K_DIM + k0 + cg * 16]);
        }
    };

#pragma unroll
    for (int p = 0; p < NSTAGE; p++) {
        issue_stage(p);
        CP_MBAR_ARRIVE(barb + p * 16);
    }

    int s = 0, fp = 0;
    for (int i = 0; i < NCHUNK; i++) {
        const uint32_t fullb  = barb + s * 16;
        const uint32_t emptyb = fullb + 8;

        MBARRIER_WAIT_PARITY(fullb, fp);

        const uint32_t sb    = smb + (uint32_t)s * STAGE_BYTES;
        const uint32_t aBase = sb + aOff;
        const uint32_t bBase = sb + A_PLANE + bOff;

#pragma unroll
        for (int kk = 0; kk < 4; kk++) {
            uint32_t a[2][4];
            LDMATRIX_X4(a[0][0], a[0][1], a[0][2], a[0][3], aBase + kk * 32);
            LDMATRIX_X4(a[1][0], a[1][1], a[1][2], a[1][3],
                        aBase + 16 * RS * 2 + kk * 32);

            uint32_t pk[8];
            LDMATRIX_X4(pk[0], pk[1], pk[2], pk[3], bBase + kk * 16);
            LDMATRIX_X4(pk[4], pk[5], pk[6], pk[7],
                        bBase + 32 * B_RS + kk * 16);

            uint32_t be[4][2];
#pragma unroll
            for (int nt = 0; nt < 4; nt++) expand_b(pk[nt], be[nt][0], be[nt][1]);
#pragma unroll
            for (int mt = 0; mt < 2; mt++)
#pragma unroll
                for (int nt = 0; nt < 4; nt++)
                    mma_f16(c[mt][nt], a[mt][0], a[mt][1], a[mt][2], a[mt][3],
                            be[nt][0], be[nt][1]);
#pragma unroll
            for (int nt = 0; nt < 4; nt++) expand_b(pk[nt + 4], be[nt][0], be[nt][1]);
#pragma unroll
            for (int mt = 0; mt < 2; mt++)
#pragma unroll
                for (int nt = 0; nt < 4; nt++)
                    mma_f16(c[mt][nt + 4], a[mt][0], a[mt][1], a[mt][2], a[mt][3],
                            be[nt][0], be[nt][1]);
        }

        if (lane == 0) MBARRIER_ARRIVE(emptyb);

        if (i + NSTAGE < NCHUNK) {
            MBARRIER_WAIT_PARITY(emptyb, fp);
            issue_stage(i + NSTAGE);
            CP_MBAR_ARRIVE(fullb);
        }

        if (++s == NSTAGE) { s = 0; fp ^= 1; }
    }

    // ---- epilogue: out = (acc - 72*rowsum) / scale[f] ----
    const int row0 = bm + warp_m * 32 + (lane >> 2);
    const int col0 = bn + warp_n * 64 + (lane & 3) * 2;
#pragma unroll
    for (int mt = 0; mt < 2; mt++) {
        const int r = row0 + mt * 16;
        const float corr0 = 72.0f * g_rsum[r];
        const float corr1 = 72.0f * g_rsum[r + 8];
#pragma unroll
        for (int nt = 0; nt < 8; nt++) {
            int col = col0 + nt * 8;
            float inv0 = 1.0f / S[col];
            float inv1 = 1.0f / S[col + 1];
            float2 v0 = make_float2((c[mt][nt][0] - corr0) * inv0,
                                    (c[mt][nt][1] - corr0) * inv1);
            float2 v1 = make_float2((c[mt][nt][2] - corr1) * inv0,
                                    (c[mt][nt][3] - corr1) * inv1);
            *reinterpret_cast<float2*>(&C[(size_t)r * N_DIM + col])       = v0;
            *reinterpret_cast<float2*>(&C[(size_t)(r + 8) * N_DIM + col]) = v1;
        }
    }
}

// ---------------- launch ----------------
extern "C" void kernel_launch(void* const* d_in, const int* in_sizes, int n_in,
                              void* d_out, int out_size) {
    int ai = 0, si = 2, wi = 1;
    for (int i = 0; i < n_in; i++) {
        if (in_sizes[i] == M_DIM * K_DIM) ai = i;
        else if (in_sizes[i] == N_DIM)    si = i;
        else                              wi = i;
    }
    const float* A = (const float*)d_in[ai];
    const void*  W = d_in[wi];
    const float* S = (const float*)d_in[si];
    float*       C = (float*)d_out;

    int hint = -1;
    if (in_sizes[wi] == W_ELEMS / 2)      hint = FMT_PACKED2;
    else if (in_sizes[wi] == W_ELEMS / 8) hint = FMT_PACKED8;

    static bool attr_done = false;
    if (!attr_done) {
        cudaFuncSetAttribute(int4_gemm_kernel,
                             cudaFuncAttributeMaxDynamicSharedMemorySize, SMEM_TOTAL);
        attr_done = true;
    }

    probe_kernel<<<1, 32>>>((const uint32_t*)W, hint);
    convert_pack_kernel<<<(N_DIM / 32) * (K_DIM / 32) / 8, 256>>>(W);
    a_prep_kernel<<<(M_DIM * 32) / 256, 256>>>(A);   // fused convert + rowsum

    dim3 grid(M_DIM / 128, N_DIM / 128);     // (8, 128) -- bm fastest
    int4_gemm_kernel<<<grid, 256, SMEM_TOTAL>>>(S, C);
}